// round 4
// baseline (speedup 1.0000x reference)
#include <cuda_runtime.h>
#include <cuda_bf16.h>
#include <math.h>

// Problem dims
#define BB 32
#define TT 256
#define EE 512
#define HH 512
#define GG 2048   // 4*H
#define CC 9
#define MTOT (BB*TT)          // 8192
#define LSTM_BLOCKS 128       // 64 per direction
#define LP 516                // padded pitch (words) for Ws / hs rows
#define LSTM_SMEM_FLOATS (64*LP + 8192)
#define LSTM_SMEM_BYTES (LSTM_SMEM_FLOATS*4)

// ---------------- device scratch (static, no runtime allocation) -------------
__device__ float g_x[MTOT*EE];                 // gathered embeddings [m][512]
__device__ float g_xp[2L*TT*BB*GG];            // [d][t][blk(64)][typ(4)][b(32)][col(8)]
__device__ float g_hcat[(size_t)MTOT*1024];    // [b*256+t][hf(512)|hb(512)]
__device__ float g_hst[3*2*BB*HH];             // [par][dir][b][k]
__device__ float g_emis[MTOT*CC];              // [b*256+t][9]
__device__ float g_llh[BB];
__device__ int   g_flags[LSTM_BLOCKS];
__device__ unsigned g_barcnt;                  // zero-initialized at load
__device__ unsigned g_bargen;
__device__ int   g_dummy_sink;

__device__ __forceinline__ int ld_acq(const int* p) {
    int v;
    asm volatile("ld.acquire.gpu.global.b32 %0, [%1];" : "=r"(v) : "l"(p));
    return v;
}
__device__ __forceinline__ void st_rel(int* p, int v) {
    asm volatile("st.release.gpu.global.b32 [%0], %1;" :: "l"(p), "r"(v));
}
__device__ __forceinline__ void cp16(float* smem_dst, const float* gsrc) {
    unsigned sa = (unsigned)__cvta_generic_to_shared(smem_dst);
    asm volatile("cp.async.cg.shared.global [%0], [%1], 16;" :: "r"(sa), "l"(gsrc));
}

// ---------------- kernel 1: embedding gather (zero row 0) --------------------
__global__ void k_gather(const int* __restrict__ inp, const float* __restrict__ emb) {
    int m = blockIdx.x;
    int tok = inp[m];
    float4* dst = (float4*)(g_x + (size_t)m * EE);
    if (tok == 0) {
        float4 z = make_float4(0.f, 0.f, 0.f, 0.f);
        for (int i = threadIdx.x; i < EE/4; i += blockDim.x) dst[i] = z;
    } else {
        const float4* src = (const float4*)(emb + (size_t)tok * EE);
        for (int i = threadIdx.x; i < EE/4; i += blockDim.x) dst[i] = src[i];
    }
}

// ---------------- kernel 2: xp = x @ W_ih^T + b_ih + b_hh  (both dirs) -------
__global__ __launch_bounds__(256, 2) void k_xpgemm(
    const float* __restrict__ wf, const float* __restrict__ wb,
    const float* __restrict__ bihf, const float* __restrict__ bhhf,
    const float* __restrict__ bihb, const float* __restrict__ bhhb)
{
    __shared__ float As[8][132];
    __shared__ float Bs[8][132];

    int ntile = blockIdx.x;            // 0..31 over 4096 cols
    int m0 = blockIdx.y * 128;
    int dir = (ntile >= 16) ? 1 : 0;
    int nloc0 = (ntile & 15) * 128;
    const float* w   = dir ? wb : wf;
    const float* bih = dir ? bihb : bihf;
    const float* bhh = dir ? bhhb : bhhf;

    int tid = threadIdx.x;
    int tx = tid & 15, ty = tid >> 4;
    int lrow = tid >> 1;
    int lk4  = (tid & 1) * 4;

    float acc[8][8];
#pragma unroll
    for (int i = 0; i < 8; i++)
#pragma unroll
        for (int j = 0; j < 8; j++) acc[i][j] = 0.f;

    for (int kt = 0; kt < EE; kt += 8) {
        float4 av = *(const float4*)(g_x + (size_t)(m0 + lrow) * EE + kt + lk4);
        float4 bv = *(const float4*)(w   + (size_t)(nloc0 + lrow) * EE + kt + lk4);
        As[lk4+0][lrow] = av.x; As[lk4+1][lrow] = av.y;
        As[lk4+2][lrow] = av.z; As[lk4+3][lrow] = av.w;
        Bs[lk4+0][lrow] = bv.x; Bs[lk4+1][lrow] = bv.y;
        Bs[lk4+2][lrow] = bv.z; Bs[lk4+3][lrow] = bv.w;
        __syncthreads();
#pragma unroll
        for (int k = 0; k < 8; k++) {
            float4 a0 = *(const float4*)&As[k][ty*4];
            float4 a1 = *(const float4*)&As[k][64 + ty*4];
            float4 b0 = *(const float4*)&Bs[k][tx*4];
            float4 b1 = *(const float4*)&Bs[k][64 + tx*4];
            float aa[8] = {a0.x,a0.y,a0.z,a0.w,a1.x,a1.y,a1.z,a1.w};
            float bb[8] = {b0.x,b0.y,b0.z,b0.w,b1.x,b1.y,b1.z,b1.w};
#pragma unroll
            for (int i = 0; i < 8; i++)
#pragma unroll
                for (int j = 0; j < 8; j++) acc[i][j] += aa[i]*bb[j];
        }
        __syncthreads();
    }

    int rws[8];
#pragma unroll
    for (int i = 0; i < 4; i++) { rws[i] = ty*4 + i; rws[4+i] = 64 + ty*4 + i; }

    float4 bias[2];
#pragma unroll
    for (int h = 0; h < 2; h++) {
        int g0 = nloc0 + h*64 + tx*4;
        bias[h] = make_float4(bih[g0+0]+bhh[g0+0], bih[g0+1]+bhh[g0+1],
                              bih[g0+2]+bhh[g0+2], bih[g0+3]+bhh[g0+3]);
    }
#pragma unroll
    for (int i = 0; i < 8; i++) {
        int m = m0 + rws[i];
        int bidx = m >> 8, t = m & 255;
        size_t tb = ((size_t)(dir*TT + t) * 64);
#pragma unroll
        for (int h = 0; h < 2; h++) {
            int g0 = nloc0 + h*64 + tx*4;
            int typ = g0 >> 9, c9 = g0 & 511;
            int blk = c9 >> 3, off = c9 & 7;        // off in {0,4}
            float4 v = make_float4(acc[i][h*4+0] + bias[h].x,
                                   acc[i][h*4+1] + bias[h].y,
                                   acc[i][h*4+2] + bias[h].z,
                                   acc[i][h*4+3] + bias[h].w);
            *(float4*)&g_xp[(tb + blk) * 1024 + typ*256 + bidx*8 + off] = v;
        }
    }
}

// ---------------- dummy kernel (shifts ncu -s window onto k_lstm) ------------
__global__ void k_dummy() { if (threadIdx.x == 1234567) g_dummy_sink = 1; }

// ---------------- kernel 3: persistent bidirectional LSTM --------------------
__device__ __forceinline__ float sigf(float x) { return 1.f / (1.f + __expf(-x)); }

__global__ __launch_bounds__(256, 1) void k_lstm(
    const float* __restrict__ whhf, const float* __restrict__ whhb)
{
    extern __shared__ float sm[];
    float* Ws  = sm;              // [32][LP]  rows r = typ*8+col
    float* hs  = sm + 32*LP;      // [32][LP]  b-major
    float* red = sm + 64*LP;      // [8 kg][4 typ][32 b][8 col]

    int bx = blockIdx.x;
    int d = bx >> 6;                   // direction
    int blk = bx & 63;
    int colbase = blk * 8;
    int tid = threadIdx.x;
    const float* whh = d ? whhb : whhf;

    // load this block's 32 W_hh rows into smem
    for (int q = tid; q < 32*128; q += 256) {
        int r = q >> 7, k4 = (q & 127) * 4;
        int grow = (r >> 3) * HH + colbase + (r & 7);
        *(float4*)(Ws + r*LP + k4) = *(const float4*)(whh + (size_t)grow * HH + k4);
    }
    if (tid == 0) ((volatile int*)g_flags)[bx] = 0;
    __threadfence();
    // one-shot grid barrier (monotone generation, replay-safe)
    if (tid == 0) {
        unsigned gen = ((volatile unsigned*)&g_bargen)[0];
        if (atomicAdd(&g_barcnt, 1u) == (unsigned)(gridDim.x - 1)) {
            g_barcnt = 0u;
            __threadfence();
            atomicAdd(&g_bargen, 1u);
        } else {
            while (((volatile unsigned*)&g_bargen)[0] == gen) { }
        }
    }
    __syncthreads();

    int lane = tid & 31;
    int kg = tid >> 5;                 // warp = K-group, K slice [kg*64, kg*64+64)
    int rg = lane >> 2;                // 0..7 gate-col within block
    int bg = lane & 3;                 // 0..3 batch group (b = bg + 4u)
    int k0 = kg * 64;
    int pcol = tid & 7, pb = tid >> 3; // phase-2 cell (b, col)
    float c = 0.f;

    for (int t = 0; t < TT; t++) {
        int par_in = t % 3, par_out = (t + 1) % 3;
        int tt = d ? (TT - 1 - t) : t;

        // prefetch xp for our cell (independent of h)
        float xg0, xg1, xg2, xg3;
        {
            const float* xr = g_xp + ((size_t)(d*TT + tt) * 64 + blk) * 1024 + pb*8 + pcol;
            xg0 = xr[0]; xg1 = xr[256]; xg2 = xr[512]; xg3 = xr[768];
        }

        float acc[4][8];
#pragma unroll
        for (int i = 0; i < 4; i++)
#pragma unroll
            for (int u = 0; u < 8; u++) acc[i][u] = 0.f;

        if (t > 0) {
            // warp-local poll: this warp depends on 8 producer blocks only
            if (lane < 8) {
                const int* fp = g_flags + d*64 + kg*8 + lane;
                while (ld_acq(fp) < t) { }
            }
            __syncwarp();
            // stage this warp's h slice via cp.async (L2-coherent, no reg pressure)
            {
                const float* src = g_hst + (size_t)((par_in*2 + d)*32) * 512 + k0;
#pragma unroll
                for (int i = 0; i < 16; i++) {
                    int q = i*32 + lane;
                    int b = q >> 4, kq = (q & 15) * 4;
                    cp16(hs + b*LP + k0 + kq, src + b*512 + kq);
                }
                asm volatile("cp.async.commit_group;");
                asm volatile("cp.async.wait_group 0;");
            }
            __syncwarp();

            // K-split GEMM: acc[i][u] += sum_k W[i*8+rg][k] * h[bg+4u][k]
            // hv streamed one at a time -> low register pressure, no spills
#pragma unroll 2
            for (int kc = 0; kc < 64; kc += 4) {
                int k = k0 + kc;
                float4 wv0 = *(const float4*)(Ws + (0*8 + rg)*LP + k);
                float4 wv1 = *(const float4*)(Ws + (1*8 + rg)*LP + k);
                float4 wv2 = *(const float4*)(Ws + (2*8 + rg)*LP + k);
                float4 wv3 = *(const float4*)(Ws + (3*8 + rg)*LP + k);
#pragma unroll
                for (int u = 0; u < 8; u++) {
                    float4 hv = *(const float4*)(hs + (bg + 4*u)*LP + k);
                    acc[0][u] += wv0.x*hv.x; acc[0][u] += wv0.y*hv.y;
                    acc[0][u] += wv0.z*hv.z; acc[0][u] += wv0.w*hv.w;
                    acc[1][u] += wv1.x*hv.x; acc[1][u] += wv1.y*hv.y;
                    acc[1][u] += wv1.z*hv.z; acc[1][u] += wv1.w*hv.w;
                    acc[2][u] += wv2.x*hv.x; acc[2][u] += wv2.y*hv.y;
                    acc[2][u] += wv2.z*hv.z; acc[2][u] += wv2.w*hv.w;
                    acc[3][u] += wv3.x*hv.x; acc[3][u] += wv3.y*hv.y;
                    acc[3][u] += wv3.z*hv.z; acc[3][u] += wv3.w*hv.w;
                }
            }
        }
        // write partials: red[kg][i][b][col]  (bank = bg*8+rg: conflict-free)
#pragma unroll
        for (int i = 0; i < 4; i++)
#pragma unroll
            for (int u = 0; u < 8; u++)
                red[kg*1024 + i*256 + (bg + 4*u)*8 + rg] = acc[i][u];
        __syncthreads();

        // phase 2: reduce K-groups, nonlinearity, write h
        float h;
        {
            float s0 = xg0, s1 = xg1, s2 = xg2, s3 = xg3;
#pragma unroll
            for (int g2 = 0; g2 < 8; g2++) {
                s0 += red[g2*1024 + 0*256 + tid];
                s1 += red[g2*1024 + 1*256 + tid];
                s2 += red[g2*1024 + 2*256 + tid];
                s3 += red[g2*1024 + 3*256 + tid];
            }
            c = sigf(s1) * c + sigf(s0) * tanhf(s2);
            h = sigf(s3) * tanhf(c);
            __stcg(&g_hst[((size_t)(par_out*2 + d)*32 + pb)*512 + colbase + pcol], h);
        }
        __threadfence();     // make h stores GPU-visible before flag release
        __syncthreads();
        if (tid == 0) st_rel(&g_flags[bx], t + 1);
        // off critical path
        g_hcat[((size_t)(pb*TT + tt))*1024 + d*HH + colbase + pcol] = h;
    }
}

// ---------------- kernel 4: classifier (emissions) ---------------------------
__global__ void k_cls(const float* __restrict__ cw, const float* __restrict__ cb) {
    __shared__ float hsm[1024];
    int m = blockIdx.x;
    const float4* src = (const float4*)(g_hcat + (size_t)m * 1024);
    for (int i = threadIdx.x; i < 256; i += blockDim.x) ((float4*)hsm)[i] = src[i];
    __syncthreads();
    int w = threadIdx.x >> 5, lane = threadIdx.x & 31;
    if (w < CC) {
        const float* wr = cw + w * 1024;
        float s = 0.f;
        for (int j = lane; j < 1024; j += 32) s += hsm[j] * wr[j];
#pragma unroll
        for (int off = 16; off; off >>= 1) s += __shfl_down_sync(0xffffffffu, s, off);
        if (lane == 0) g_emis[(size_t)m * CC + w] = s + cb[w];
    }
}

// ---------------- kernel 5: CRF log-likelihood (mask all-true) ---------------
__global__ void k_crf(const int* __restrict__ label, const float* __restrict__ startv,
                      const float* __restrict__ endv, const float* __restrict__ trans) {
    int b = blockIdx.x, lane = threadIdx.x;
    const int* tg = label + b * TT;
    const float* em = g_emis + (size_t)b * TT * CC;

    float p = 0.f;
    for (int t = lane; t < TT; t += 32) {
        int tag = tg[t];
        p += em[t*CC + tag];
        if (t > 0) p += trans[tg[t-1]*CC + tag];
    }
#pragma unroll
    for (int off = 16; off; off >>= 1) p += __shfl_down_sync(0xffffffffu, p, off);
    float num = __shfl_sync(0xffffffffu, p, 0);
    num += startv[tg[0]] + endv[tg[TT-1]];

    int j = (lane < CC) ? lane : 0;
    float trc[CC];
#pragma unroll
    for (int i = 0; i < CC; i++) trc[i] = trans[i*CC + j];
    float alpha = startv[j] + em[j];
    float em_next = em[CC + j];
    for (int t = 1; t < TT; t++) {
        float a[CC];
#pragma unroll
        for (int i = 0; i < CC; i++) a[i] = __shfl_sync(0xffffffffu, alpha, i) + trc[i];
        float em_t = em_next;
        if (t < TT-1) em_next = em[(t+1)*CC + j];
        float mx = a[0];
#pragma unroll
        for (int i = 1; i < CC; i++) mx = fmaxf(mx, a[i]);
        float s = 0.f;
#pragma unroll
        for (int i = 0; i < CC; i++) s += expf(a[i] - mx);
        alpha = mx + logf(s) + em_t;
    }
    float v = alpha + endv[j];
    float mv = v;
#pragma unroll
    for (int i = 0; i < CC; i++) mv = fmaxf(mv, __shfl_sync(0xffffffffu, v, i));
    float se = expf(v - mv);
    float tot = 0.f;
#pragma unroll
    for (int i = 0; i < CC; i++) tot += __shfl_sync(0xffffffffu, se, i);
    float den = mv + logf(tot);
    if (lane == 0) g_llh[b] = num - den;
}

// ---------------- kernel 6: final reduction ----------------------------------
__global__ void k_final(float* out) {
    if (threadIdx.x == 0) {
        float s = 0.f;
        for (int i = 0; i < BB; i++) s += g_llh[i];
        out[0] = -s / (float)BB;
    }
}

// ---------------- launch ------------------------------------------------------
extern "C" void kernel_launch(void* const* d_in, const int* in_sizes, int n_in,
                              void* d_out, int out_size) {
    const int*   input  = (const int*)d_in[0];
    const int*   label  = (const int*)d_in[1];
    const float* emb    = (const float*)d_in[2];
    const float* w_ih_f = (const float*)d_in[3];
    const float* w_hh_f = (const float*)d_in[4];
    const float* b_ih_f = (const float*)d_in[5];
    const float* b_hh_f = (const float*)d_in[6];
    const float* w_ih_b = (const float*)d_in[7];
    const float* w_hh_b = (const float*)d_in[8];
    const float* b_ih_b = (const float*)d_in[9];
    const float* b_hh_b = (const float*)d_in[10];
    const float* cls_w  = (const float*)d_in[11];
    const float* cls_b  = (const float*)d_in[12];
    const float* startv = (const float*)d_in[13];
    const float* endv   = (const float*)d_in[14];
    const float* trans  = (const float*)d_in[15];

    cudaFuncSetAttribute(k_lstm, cudaFuncAttributeMaxDynamicSharedMemorySize, LSTM_SMEM_BYTES);

    k_gather<<<MTOT, 128>>>(input, emb);
    k_xpgemm<<<dim3(32, 64), 256>>>(w_ih_f, w_ih_b, b_ih_f, b_hh_f, b_ih_b, b_hh_b);
    k_dummy<<<1, 32>>>();   // shifts ncu's -s 5 -c 1 window onto k_lstm
    k_lstm<<<LSTM_BLOCKS, 256, LSTM_SMEM_BYTES>>>(w_hh_f, w_hh_b);
    k_cls<<<MTOT, 288>>>(cls_w, cls_b);
    k_crf<<<BB, 32>>>(label, startv, endv, trans);
    k_final<<<1, 32>>>((float*)d_out);
}

// round 6
// speedup vs baseline: 1.2443x; 1.2443x over previous
#include <cuda_runtime.h>
#include <cuda_bf16.h>
#include <math.h>

// Problem dims
#define BB 32
#define TT 256
#define EE 512
#define HH 512
#define GG 2048   // 4*H
#define CC 9
#define MTOT (BB*TT)          // 8192
#define LSTM_BLOCKS 128       // 64 per direction
#define LP 516                // padded pitch (words) for Ws rows
#define LSTM_SMEM_FLOATS (32*LP + 8192)
#define LSTM_SMEM_BYTES (LSTM_SMEM_FLOATS*4)

// ---------------- device scratch (static, no runtime allocation) -------------
__device__ float g_x[MTOT*EE];                 // gathered embeddings [m][512]
__device__ float g_xp[2L*TT*BB*GG];            // [d][t][blk(64)][typ(4)][b(32)][col(8)]
__device__ float g_hcat[(size_t)MTOT*1024];    // [b*256+t][hf(512)|hb(512)]
__device__ float g_hst[3*2*BB*HH];             // [par][dir][b][k]
__device__ float g_emis[MTOT*CC];              // [b*256+t][9]
__device__ float g_llh[BB];
__device__ int   g_flags[LSTM_BLOCKS];
__device__ unsigned g_barcnt;                  // zero-initialized at load
__device__ unsigned g_bargen;
__device__ int   g_dummy_sink;

__device__ __forceinline__ int ld_acq(const int* p) {
    int v;
    asm volatile("ld.acquire.gpu.global.b32 %0, [%1];" : "=r"(v) : "l"(p));
    return v;
}
__device__ __forceinline__ void st_rel(int* p, int v) {
    asm volatile("st.release.gpu.global.b32 [%0], %1;" :: "l"(p), "r"(v));
}

// ---------------- kernel 1: embedding gather (zero row 0) --------------------
__global__ void k_gather(const int* __restrict__ inp, const float* __restrict__ emb) {
    int m = blockIdx.x;
    int tok = inp[m];
    float4* dst = (float4*)(g_x + (size_t)m * EE);
    if (tok == 0) {
        float4 z = make_float4(0.f, 0.f, 0.f, 0.f);
        for (int i = threadIdx.x; i < EE/4; i += blockDim.x) dst[i] = z;
    } else {
        const float4* src = (const float4*)(emb + (size_t)tok * EE);
        for (int i = threadIdx.x; i < EE/4; i += blockDim.x) dst[i] = src[i];
    }
}

// ---------------- kernel 2: xp = x @ W_ih^T + b_ih + b_hh  (both dirs) -------
__global__ __launch_bounds__(256, 2) void k_xpgemm(
    const float* __restrict__ wf, const float* __restrict__ wb,
    const float* __restrict__ bihf, const float* __restrict__ bhhf,
    const float* __restrict__ bihb, const float* __restrict__ bhhb)
{
    __shared__ float As[8][132];
    __shared__ float Bs[8][132];

    int ntile = blockIdx.x;            // 0..31 over 4096 cols
    int m0 = blockIdx.y * 128;
    int dir = (ntile >= 16) ? 1 : 0;
    int nloc0 = (ntile & 15) * 128;
    const float* w   = dir ? wb : wf;
    const float* bih = dir ? bihb : bihf;
    const float* bhh = dir ? bhhb : bhhf;

    int tid = threadIdx.x;
    int tx = tid & 15, ty = tid >> 4;
    int lrow = tid >> 1;
    int lk4  = (tid & 1) * 4;

    float acc[8][8];
#pragma unroll
    for (int i = 0; i < 8; i++)
#pragma unroll
        for (int j = 0; j < 8; j++) acc[i][j] = 0.f;

    for (int kt = 0; kt < EE; kt += 8) {
        float4 av = *(const float4*)(g_x + (size_t)(m0 + lrow) * EE + kt + lk4);
        float4 bv = *(const float4*)(w   + (size_t)(nloc0 + lrow) * EE + kt + lk4);
        As[lk4+0][lrow] = av.x; As[lk4+1][lrow] = av.y;
        As[lk4+2][lrow] = av.z; As[lk4+3][lrow] = av.w;
        Bs[lk4+0][lrow] = bv.x; Bs[lk4+1][lrow] = bv.y;
        Bs[lk4+2][lrow] = bv.z; Bs[lk4+3][lrow] = bv.w;
        __syncthreads();
#pragma unroll
        for (int k = 0; k < 8; k++) {
            float4 a0 = *(const float4*)&As[k][ty*4];
            float4 a1 = *(const float4*)&As[k][64 + ty*4];
            float4 b0 = *(const float4*)&Bs[k][tx*4];
            float4 b1 = *(const float4*)&Bs[k][64 + tx*4];
            float aa[8] = {a0.x,a0.y,a0.z,a0.w,a1.x,a1.y,a1.z,a1.w};
            float bb[8] = {b0.x,b0.y,b0.z,b0.w,b1.x,b1.y,b1.z,b1.w};
#pragma unroll
            for (int i = 0; i < 8; i++)
#pragma unroll
                for (int j = 0; j < 8; j++) acc[i][j] += aa[i]*bb[j];
        }
        __syncthreads();
    }

    int rws[8];
#pragma unroll
    for (int i = 0; i < 4; i++) { rws[i] = ty*4 + i; rws[4+i] = 64 + ty*4 + i; }

    float4 bias[2];
#pragma unroll
    for (int h = 0; h < 2; h++) {
        int g0 = nloc0 + h*64 + tx*4;
        bias[h] = make_float4(bih[g0+0]+bhh[g0+0], bih[g0+1]+bhh[g0+1],
                              bih[g0+2]+bhh[g0+2], bih[g0+3]+bhh[g0+3]);
    }
#pragma unroll
    for (int i = 0; i < 8; i++) {
        int m = m0 + rws[i];
        int bidx = m >> 8, t = m & 255;
        size_t tb = ((size_t)(dir*TT + t) * 64);
#pragma unroll
        for (int h = 0; h < 2; h++) {
            int g0 = nloc0 + h*64 + tx*4;
            int typ = g0 >> 9, c9 = g0 & 511;
            int blk = c9 >> 3, off = c9 & 7;        // off in {0,4}
            float4 v = make_float4(acc[i][h*4+0] + bias[h].x,
                                   acc[i][h*4+1] + bias[h].y,
                                   acc[i][h*4+2] + bias[h].z,
                                   acc[i][h*4+3] + bias[h].w);
            *(float4*)&g_xp[(tb + blk) * 1024 + typ*256 + bidx*8 + off] = v;
        }
    }
}

// ---------------- dummy kernel (shifts ncu -s window onto k_lstm) ------------
__global__ void k_dummy() { if (threadIdx.x == 1234567) g_dummy_sink = 1; }

// ---------------- kernel 3: persistent bidirectional LSTM --------------------
// 128 blocks (64/dir), 512 threads. Block owns 8 h-columns. 16 warps:
// warp w -> k-slice kg=w&7 (k in [kg*64,kg*64+64)), batch-half half=w>>3.
// Per step, each warp walks its 8 producer slices independently:
//   poll producer flag -> ldcg slice from L2 -> FMA. No smem h staging.
__device__ __forceinline__ float sigf(float x) { return 1.f / (1.f + __expf(-x)); }

__global__ __launch_bounds__(512, 1) void k_lstm(
    const float* __restrict__ whhf, const float* __restrict__ whhb)
{
    extern __shared__ float sm[];
    float* Ws  = sm;              // [32][LP]  rows r = typ*8+col
    float* red = sm + 32*LP;      // [8 kg][4 typ][32 b][8 col]

    int bx = blockIdx.x;
    int d = bx >> 6;                   // direction
    int blk = bx & 63;
    int colbase = blk * 8;
    int tid = threadIdx.x;
    const float* whh = d ? whhb : whhf;

    // load this block's 32 W_hh rows into smem
    for (int q = tid; q < 32*128; q += 512) {
        int r = q >> 7, k4 = (q & 127) * 4;
        int grow = (r >> 3) * HH + colbase + (r & 7);
        *(float4*)(Ws + r*LP + k4) = *(const float4*)(whh + (size_t)grow * HH + k4);
    }
    if (tid == 0) ((volatile int*)g_flags)[bx] = 0;
    __threadfence();
    // one-shot grid barrier (monotone generation, replay-safe)
    if (tid == 0) {
        unsigned gen = ((volatile unsigned*)&g_bargen)[0];
        if (atomicAdd(&g_barcnt, 1u) == (unsigned)(gridDim.x - 1)) {
            g_barcnt = 0u;
            __threadfence();
            atomicAdd(&g_bargen, 1u);
        } else {
            while (((volatile unsigned*)&g_bargen)[0] == gen) { }
        }
    }
    __syncthreads();

    int lane = tid & 31;
    int w = tid >> 5;
    int kg = w & 7;                    // k-slice [kg*64, kg*64+64)
    int half = w >> 3;                 // batch half: b = bg + 4*(half*4+u)
    int rg = lane >> 2;                // 0..7 gate-col within block
    int bg = lane & 3;                 // 0..3 batch group
    int pcol = tid & 7, pb = tid >> 3; // phase-2 cell (tid<256): (b=pb, col=pcol)
    float c = 0.f;

    for (int t = 0; t < TT; t++) {
        int par_in = t % 3, par_out = (t + 1) % 3;
        int tt = d ? (TT - 1 - t) : t;

        // prefetch xp for our cell (independent of h)
        float xg0 = 0.f, xg1 = 0.f, xg2 = 0.f, xg3 = 0.f;
        if (tid < 256) {
            const float* xr = g_xp + ((size_t)(d*TT + tt) * 64 + blk) * 1024 + tid;
            xg0 = xr[0]; xg1 = xr[256]; xg2 = xr[512]; xg3 = xr[768];
        }

        float acc[4][4];
#pragma unroll
        for (int i = 0; i < 4; i++)
#pragma unroll
            for (int u = 0; u < 4; u++) acc[i][u] = 0.f;

        if (t > 0) {
            const float* hbase = g_hst + (size_t)((par_in*2 + d)*32) * 512;
            int s = blk & 7;           // decorrelate poll order across blocks
#pragma unroll 1
            for (int jj = 0; jj < 8; jj++) {
                int j = (jj + s) & 7;
                int p = kg*8 + j;      // producer block (within dir)
                int k = p * 8;         // global k base of this 8-wide slice
                const int* fp = g_flags + d*64 + p;
                if (lane == 0) { while (ld_acq(fp) < t) { } }
                __syncwarp();          // carries acquire ordering to all lanes
                // read slice straight from L2 into registers (8-lane dedup)
                float4 hv[2][4];
#pragma unroll
                for (int u = 0; u < 4; u++) {
                    const float* hb = hbase + (size_t)(bg + 4*(half*4+u)) * 512 + k;
                    hv[0][u] = __ldcg((const float4*)hb);
                    hv[1][u] = __ldcg((const float4*)(hb + 4));
                }
#pragma unroll
                for (int c2 = 0; c2 < 2; c2++) {
                    int kk = k + c2*4;
                    float4 wv0 = *(const float4*)(Ws + (0*8 + rg)*LP + kk);
                    float4 wv1 = *(const float4*)(Ws + (1*8 + rg)*LP + kk);
                    float4 wv2 = *(const float4*)(Ws + (2*8 + rg)*LP + kk);
                    float4 wv3 = *(const float4*)(Ws + (3*8 + rg)*LP + kk);
#pragma unroll
                    for (int u = 0; u < 4; u++) {
                        float4 hvv = hv[c2][u];
                        acc[0][u] += wv0.x*hvv.x; acc[0][u] += wv0.y*hvv.y;
                        acc[0][u] += wv0.z*hvv.z; acc[0][u] += wv0.w*hvv.w;
                        acc[1][u] += wv1.x*hvv.x; acc[1][u] += wv1.y*hvv.y;
                        acc[1][u] += wv1.z*hvv.z; acc[1][u] += wv1.w*hvv.w;
                        acc[2][u] += wv2.x*hvv.x; acc[2][u] += wv2.y*hvv.y;
                        acc[2][u] += wv2.z*hvv.z; acc[2][u] += wv2.w*hvv.w;
                        acc[3][u] += wv3.x*hvv.x; acc[3][u] += wv3.y*hvv.y;
                        acc[3][u] += wv3.z*hvv.z; acc[3][u] += wv3.w*hvv.w;
                    }
                }
            }
        }
        // write partials: red[kg][i][b][col]  (bank = bg*8+rg: conflict-free)
#pragma unroll
        for (int i = 0; i < 4; i++)
#pragma unroll
            for (int u = 0; u < 4; u++)
                red[kg*1024 + i*256 + (bg + 4*(half*4+u))*8 + rg] = acc[i][u];
        __syncthreads();

        // phase 2: reduce K-groups, nonlinearity, write h (threads 0..255)
        float h = 0.f;
        if (tid < 256) {
            float s0 = xg0, s1 = xg1, s2 = xg2, s3 = xg3;
#pragma unroll
            for (int g2 = 0; g2 < 8; g2++) {
                s0 += red[g2*1024 + 0*256 + tid];
                s1 += red[g2*1024 + 1*256 + tid];
                s2 += red[g2*1024 + 2*256 + tid];
                s3 += red[g2*1024 + 3*256 + tid];
            }
            c = sigf(s1) * c + sigf(s0) * tanhf(s2);
            h = sigf(s3) * tanhf(c);
            __stcg(&g_hst[((size_t)(par_out*2 + d)*32 + pb)*512 + colbase + pcol], h);
        }
        __syncthreads();   // h stores happen-before tid0's release (PTX model)
        if (tid == 0) st_rel(&g_flags[bx], t + 1);
        // off critical path
        if (tid < 256)
            g_hcat[((size_t)(pb*TT + tt))*1024 + d*HH + colbase + pcol] = h;
    }
}

// ---------------- kernel 4: classifier (emissions) ---------------------------
__global__ void k_cls(const float* __restrict__ cw, const float* __restrict__ cb) {
    __shared__ float hsm[1024];
    int m = blockIdx.x;
    const float4* src = (const float4*)(g_hcat + (size_t)m * 1024);
    for (int i = threadIdx.x; i < 256; i += blockDim.x) ((float4*)hsm)[i] = src[i];
    __syncthreads();
    int w = threadIdx.x >> 5, lane = threadIdx.x & 31;
    if (w < CC) {
        const float* wr = cw + w * 1024;
        float s = 0.f;
        for (int j = lane; j < 1024; j += 32) s += hsm[j] * wr[j];
#pragma unroll
        for (int off = 16; off; off >>= 1) s += __shfl_down_sync(0xffffffffu, s, off);
        if (lane == 0) g_emis[(size_t)m * CC + w] = s + cb[w];
    }
}

// ---------------- kernel 5: CRF log-likelihood (mask all-true) ---------------
__global__ void k_crf(const int* __restrict__ label, const float* __restrict__ startv,
                      const float* __restrict__ endv, const float* __restrict__ trans) {
    int b = blockIdx.x, lane = threadIdx.x;
    const int* tg = label + b * TT;
    const float* em = g_emis + (size_t)b * TT * CC;

    float p = 0.f;
    for (int t = lane; t < TT; t += 32) {
        int tag = tg[t];
        p += em[t*CC + tag];
        if (t > 0) p += trans[tg[t-1]*CC + tag];
    }
#pragma unroll
    for (int off = 16; off; off >>= 1) p += __shfl_down_sync(0xffffffffu, p, off);
    float num = __shfl_sync(0xffffffffu, p, 0);
    num += startv[tg[0]] + endv[tg[TT-1]];

    int j = (lane < CC) ? lane : 0;
    float trc[CC];
#pragma unroll
    for (int i = 0; i < CC; i++) trc[i] = trans[i*CC + j];
    float alpha = startv[j] + em[j];
    float em_next = em[CC + j];
    for (int t = 1; t < TT; t++) {
        float a[CC];
#pragma unroll
        for (int i = 0; i < CC; i++) a[i] = __shfl_sync(0xffffffffu, alpha, i) + trc[i];
        float em_t = em_next;
        if (t < TT-1) em_next = em[(t+1)*CC + j];
        float mx = a[0];
#pragma unroll
        for (int i = 1; i < CC; i++) mx = fmaxf(mx, a[i]);
        float s = 0.f;
#pragma unroll
        for (int i = 0; i < CC; i++) s += expf(a[i] - mx);
        alpha = mx + logf(s) + em_t;
    }
    float v = alpha + endv[j];
    float mv = v;
#pragma unroll
    for (int i = 0; i < CC; i++) mv = fmaxf(mv, __shfl_sync(0xffffffffu, v, i));
    float se = expf(v - mv);
    float tot = 0.f;
#pragma unroll
    for (int i = 0; i < CC; i++) tot += __shfl_sync(0xffffffffu, se, i);
    float den = mv + logf(tot);
    if (lane == 0) g_llh[b] = num - den;
}

// ---------------- kernel 6: final reduction ----------------------------------
__global__ void k_final(float* out) {
    if (threadIdx.x == 0) {
        float s = 0.f;
        for (int i = 0; i < BB; i++) s += g_llh[i];
        out[0] = -s / (float)BB;
    }
}

// ---------------- launch ------------------------------------------------------
extern "C" void kernel_launch(void* const* d_in, const int* in_sizes, int n_in,
                              void* d_out, int out_size) {
    const int*   input  = (const int*)d_in[0];
    const int*   label  = (const int*)d_in[1];
    const float* emb    = (const float*)d_in[2];
    const float* w_ih_f = (const float*)d_in[3];
    const float* w_hh_f = (const float*)d_in[4];
    const float* b_ih_f = (const float*)d_in[5];
    const float* b_hh_f = (const float*)d_in[6];
    const float* w_ih_b = (const float*)d_in[7];
    const float* w_hh_b = (const float*)d_in[8];
    const float* b_ih_b = (const float*)d_in[9];
    const float* b_hh_b = (const float*)d_in[10];
    const float* cls_w  = (const float*)d_in[11];
    const float* cls_b  = (const float*)d_in[12];
    const float* startv = (const float*)d_in[13];
    const float* endv   = (const float*)d_in[14];
    const float* trans  = (const float*)d_in[15];

    cudaFuncSetAttribute(k_lstm, cudaFuncAttributeMaxDynamicSharedMemorySize, LSTM_SMEM_BYTES);

    k_gather<<<MTOT, 128>>>(input, emb);
    k_xpgemm<<<dim3(32, 64), 256>>>(w_ih_f, w_ih_b, b_ih_f, b_hh_f, b_ih_b, b_hh_b);
    k_dummy<<<1, 32>>>();   // keeps ncu window on k_lstm
    k_lstm<<<LSTM_BLOCKS, 512, LSTM_SMEM_BYTES>>>(w_hh_f, w_hh_b);
    k_cls<<<MTOT, 288>>>(cls_w, cls_b);
    k_crf<<<BB, 32>>>(label, startv, endv, trans);
    k_final<<<1, 32>>>((float*)d_out);
}

// round 7
// speedup vs baseline: 1.6635x; 1.3368x over previous
#include <cuda_runtime.h>
#include <cuda_bf16.h>
#include <math.h>

// Problem dims
#define BB 32
#define TT 256
#define EE 512
#define HH 512
#define GG 2048   // 4*H
#define CC 9
#define MTOT (BB*TT)          // 8192
#define LSTM_BLOCKS 128       // 64 per direction
#define LP 516                // padded pitch (words) for Ws rows
#define LSTM_SMEM_FLOATS (32*LP + 8192)
#define LSTM_SMEM_BYTES (LSTM_SMEM_FLOATS*4)

// ---------------- device scratch (static, no runtime allocation) -------------
__device__ float g_x[MTOT*EE];                 // gathered embeddings [m][512]
__device__ float g_xp[2L*TT*BB*GG];            // [d][t][blk(64)][typ(4)][b(32)][col(8)]
__device__ float g_hcat[(size_t)MTOT*1024];    // [b*256+t][hf(512)|hb(512)]
__device__ float g_hst[2*2*BB*HH];             // [par][dir][b][k]  double buffer
__device__ float g_emis[MTOT*CC];              // [b*256+t][9]
__device__ float g_llh[BB];
__device__ int   g_cnt[TT];                    // per-step completion counters
__device__ unsigned g_barcnt;                  // zero-initialized at load
__device__ unsigned g_bargen;
__device__ int   g_dummy_sink;

__device__ __forceinline__ int ld_acq(const int* p) {
    int v;
    asm volatile("ld.acquire.gpu.global.b32 %0, [%1];" : "=r"(v) : "l"(p));
    return v;
}
__device__ __forceinline__ void red_add_rel(int* p) {
    asm volatile("red.release.gpu.global.add.s32 [%0], %1;" :: "l"(p), "r"(1) : "memory");
}

// ---------------- kernel 1: embedding gather (zero row 0) --------------------
__global__ void k_gather(const int* __restrict__ inp, const float* __restrict__ emb) {
    int m = blockIdx.x;
    int tok = inp[m];
    float4* dst = (float4*)(g_x + (size_t)m * EE);
    if (tok == 0) {
        float4 z = make_float4(0.f, 0.f, 0.f, 0.f);
        for (int i = threadIdx.x; i < EE/4; i += blockDim.x) dst[i] = z;
    } else {
        const float4* src = (const float4*)(emb + (size_t)tok * EE);
        for (int i = threadIdx.x; i < EE/4; i += blockDim.x) dst[i] = src[i];
    }
}

// ---------------- kernel 2: xp = x @ W_ih^T + b_ih + b_hh  (both dirs) -------
__global__ __launch_bounds__(256, 2) void k_xpgemm(
    const float* __restrict__ wf, const float* __restrict__ wb,
    const float* __restrict__ bihf, const float* __restrict__ bhhf,
    const float* __restrict__ bihb, const float* __restrict__ bhhb)
{
    __shared__ float As[8][132];
    __shared__ float Bs[8][132];

    int ntile = blockIdx.x;            // 0..31 over 4096 cols
    int m0 = blockIdx.y * 128;
    int dir = (ntile >= 16) ? 1 : 0;
    int nloc0 = (ntile & 15) * 128;
    const float* w   = dir ? wb : wf;
    const float* bih = dir ? bihb : bihf;
    const float* bhh = dir ? bhhb : bhhf;

    int tid = threadIdx.x;
    int tx = tid & 15, ty = tid >> 4;
    int lrow = tid >> 1;
    int lk4  = (tid & 1) * 4;

    float acc[8][8];
#pragma unroll
    for (int i = 0; i < 8; i++)
#pragma unroll
        for (int j = 0; j < 8; j++) acc[i][j] = 0.f;

    for (int kt = 0; kt < EE; kt += 8) {
        float4 av = *(const float4*)(g_x + (size_t)(m0 + lrow) * EE + kt + lk4);
        float4 bv = *(const float4*)(w   + (size_t)(nloc0 + lrow) * EE + kt + lk4);
        As[lk4+0][lrow] = av.x; As[lk4+1][lrow] = av.y;
        As[lk4+2][lrow] = av.z; As[lk4+3][lrow] = av.w;
        Bs[lk4+0][lrow] = bv.x; Bs[lk4+1][lrow] = bv.y;
        Bs[lk4+2][lrow] = bv.z; Bs[lk4+3][lrow] = bv.w;
        __syncthreads();
#pragma unroll
        for (int k = 0; k < 8; k++) {
            float4 a0 = *(const float4*)&As[k][ty*4];
            float4 a1 = *(const float4*)&As[k][64 + ty*4];
            float4 b0 = *(const float4*)&Bs[k][tx*4];
            float4 b1 = *(const float4*)&Bs[k][64 + tx*4];
            float aa[8] = {a0.x,a0.y,a0.z,a0.w,a1.x,a1.y,a1.z,a1.w};
            float bb[8] = {b0.x,b0.y,b0.z,b0.w,b1.x,b1.y,b1.z,b1.w};
#pragma unroll
            for (int i = 0; i < 8; i++)
#pragma unroll
                for (int j = 0; j < 8; j++) acc[i][j] += aa[i]*bb[j];
        }
        __syncthreads();
    }

    int rws[8];
#pragma unroll
    for (int i = 0; i < 4; i++) { rws[i] = ty*4 + i; rws[4+i] = 64 + ty*4 + i; }

    float4 bias[2];
#pragma unroll
    for (int h = 0; h < 2; h++) {
        int g0 = nloc0 + h*64 + tx*4;
        bias[h] = make_float4(bih[g0+0]+bhh[g0+0], bih[g0+1]+bhh[g0+1],
                              bih[g0+2]+bhh[g0+2], bih[g0+3]+bhh[g0+3]);
    }
#pragma unroll
    for (int i = 0; i < 8; i++) {
        int m = m0 + rws[i];
        int bidx = m >> 8, t = m & 255;
        size_t tb = ((size_t)(dir*TT + t) * 64);
#pragma unroll
        for (int h = 0; h < 2; h++) {
            int g0 = nloc0 + h*64 + tx*4;
            int typ = g0 >> 9, c9 = g0 & 511;
            int blk = c9 >> 3, off = c9 & 7;        // off in {0,4}
            float4 v = make_float4(acc[i][h*4+0] + bias[h].x,
                                   acc[i][h*4+1] + bias[h].y,
                                   acc[i][h*4+2] + bias[h].z,
                                   acc[i][h*4+3] + bias[h].w);
            *(float4*)&g_xp[(tb + blk) * 1024 + typ*256 + bidx*8 + off] = v;
        }
    }
}

// ---------------- dummy kernel (shifts ncu -s window onto k_lstm) ------------
__global__ void k_dummy() { if (threadIdx.x == 1234567) g_dummy_sink = 1; }

// ---------------- kernel 3: persistent bidirectional LSTM --------------------
// 128 blocks (64/dir), 512 threads. Block owns 8 h-columns.
// ONE aggregated barrier per step: red.release.add to g_cnt[t]; single poller
// per block with nanosleep backoff. h double-buffered by step parity.
__device__ __forceinline__ float sigf(float x) { return 1.f / (1.f + __expf(-x)); }

__global__ __launch_bounds__(512, 1) void k_lstm(
    const float* __restrict__ whhf, const float* __restrict__ whhb)
{
    extern __shared__ float sm[];
    float* Ws  = sm;              // [32][LP]  rows r = typ*8+col
    float* red = sm + 32*LP;      // [8 kg][4 typ][32 b][8 col]

    int bx = blockIdx.x;
    int d = bx >> 6;                   // direction
    int blk = bx & 63;
    int colbase = blk * 8;
    int tid = threadIdx.x;
    const float* whh = d ? whhb : whhf;

    // load this block's 32 W_hh rows into smem
    for (int q = tid; q < 32*128; q += 512) {
        int r = q >> 7, k4 = (q & 127) * 4;
        int grow = (r >> 3) * HH + colbase + (r & 7);
        *(float4*)(Ws + r*LP + k4) = *(const float4*)(whh + (size_t)grow * HH + k4);
    }
    // block 0 zeroes the step counters (replay-safe: done before grid barrier)
    if (bx == 0) for (int q = tid; q < TT; q += 512) g_cnt[q] = 0;
    __threadfence();
    // one-shot grid barrier (monotone generation, replay-safe)
    if (tid == 0) {
        unsigned gen = ((volatile unsigned*)&g_bargen)[0];
        if (atomicAdd(&g_barcnt, 1u) == (unsigned)(gridDim.x - 1)) {
            g_barcnt = 0u;
            __threadfence();
            atomicAdd(&g_bargen, 1u);
        } else {
            while (((volatile unsigned*)&g_bargen)[0] == gen) { }
        }
    }
    __syncthreads();

    int lane = tid & 31;
    int w = tid >> 5;
    int kg = w & 7;                    // k-slice [kg*64, kg*64+64)
    int half = w >> 3;                 // batch half: b = bg + 4*(half*4+u)
    int rg = lane >> 2;                // 0..7 gate-col within block
    int bg = lane & 3;                 // 0..3 batch group
    int pcol = tid & 7, pb = tid >> 3; // phase-2 cell (tid<256): (b=pb, col=pcol)
    float c = 0.f;

    for (int t = 0; t < TT; t++) {
        int tt = d ? (TT - 1 - t) : t;

        // prefetch xp for our cell (independent of h; overlaps barrier wait)
        float xg0 = 0.f, xg1 = 0.f, xg2 = 0.f, xg3 = 0.f;
        if (tid < 256) {
            const float* xr = g_xp + ((size_t)(d*TT + tt) * 64 + blk) * 1024 + tid;
            xg0 = xr[0]; xg1 = xr[256]; xg2 = xr[512]; xg3 = xr[768];
        }

        float acc[4][4];
#pragma unroll
        for (int i = 0; i < 4; i++)
#pragma unroll
            for (int u = 0; u < 4; u++) acc[i][u] = 0.f;

        if (t > 0) {
            // single aggregated barrier: wait for all 128 blocks to finish t-1
            if (tid == 0) {
                const int* cp = &g_cnt[t-1];
                int miss = 0;
                while (ld_acq(cp) < LSTM_BLOCKS) {
                    if (++miss > 2) __nanosleep(200);
                }
            }
            __syncthreads();   // broadcasts the acquire to all threads

            // GEMM over this warp's k-slice, h read straight from L2
            const float* hbase = g_hst
                + (size_t)((((t+1)&1)*2 + d)*32) * 512;   // buf[(t-1)&1]
#pragma unroll 2
            for (int kc = 0; kc < 64; kc += 4) {
                int k = kg*64 + kc;
                float4 hv[4];
#pragma unroll
                for (int u = 0; u < 4; u++)
                    hv[u] = __ldcg((const float4*)(hbase
                              + (size_t)(bg + 4*(half*4+u)) * 512 + k));
                float4 wv0 = *(const float4*)(Ws + (0*8 + rg)*LP + k);
                float4 wv1 = *(const float4*)(Ws + (1*8 + rg)*LP + k);
                float4 wv2 = *(const float4*)(Ws + (2*8 + rg)*LP + k);
                float4 wv3 = *(const float4*)(Ws + (3*8 + rg)*LP + k);
#pragma unroll
                for (int u = 0; u < 4; u++) {
                    float4 hvv = hv[u];
                    acc[0][u] += wv0.x*hvv.x; acc[0][u] += wv0.y*hvv.y;
                    acc[0][u] += wv0.z*hvv.z; acc[0][u] += wv0.w*hvv.w;
                    acc[1][u] += wv1.x*hvv.x; acc[1][u] += wv1.y*hvv.y;
                    acc[1][u] += wv1.z*hvv.z; acc[1][u] += wv1.w*hvv.w;
                    acc[2][u] += wv2.x*hvv.x; acc[2][u] += wv2.y*hvv.y;
                    acc[2][u] += wv2.z*hvv.z; acc[2][u] += wv2.w*hvv.w;
                    acc[3][u] += wv3.x*hvv.x; acc[3][u] += wv3.y*hvv.y;
                    acc[3][u] += wv3.z*hvv.z; acc[3][u] += wv3.w*hvv.w;
                }
            }
        }
        // write partials: red[kg][i][b][col]  (bank = bg*8+rg: conflict-free)
#pragma unroll
        for (int i = 0; i < 4; i++)
#pragma unroll
            for (int u = 0; u < 4; u++)
                red[kg*1024 + i*256 + (bg + 4*(half*4+u))*8 + rg] = acc[i][u];
        __syncthreads();

        // phase 2: reduce K-groups, nonlinearity, write h (threads 0..255)
        float h = 0.f;
        if (tid < 256) {
            float s0 = xg0, s1 = xg1, s2 = xg2, s3 = xg3;
#pragma unroll
            for (int g2 = 0; g2 < 8; g2++) {
                s0 += red[g2*1024 + 0*256 + tid];
                s1 += red[g2*1024 + 1*256 + tid];
                s2 += red[g2*1024 + 2*256 + tid];
                s3 += red[g2*1024 + 3*256 + tid];
            }
            c = sigf(s1) * c + sigf(s0) * tanhf(s2);
            h = sigf(s3) * tanhf(c);
            __stcg(&g_hst[((size_t)(((t&1)*2 + d)*32) + pb)*512 + colbase + pcol], h);
        }
        __syncthreads();   // h stores happen-before tid0's release-add
        if (tid == 0) red_add_rel(&g_cnt[t]);
        // off critical path
        if (tid < 256)
            g_hcat[((size_t)(pb*TT + tt))*1024 + d*HH + colbase + pcol] = h;
    }
}

// ---------------- kernel 4: classifier (emissions) ---------------------------
__global__ void k_cls(const float* __restrict__ cw, const float* __restrict__ cb) {
    __shared__ float hsm[1024];
    int m = blockIdx.x;
    const float4* src = (const float4*)(g_hcat + (size_t)m * 1024);
    for (int i = threadIdx.x; i < 256; i += blockDim.x) ((float4*)hsm)[i] = src[i];
    __syncthreads();
    int w = threadIdx.x >> 5, lane = threadIdx.x & 31;
    if (w < CC) {
        const float* wr = cw + w * 1024;
        float s = 0.f;
        for (int j = lane; j < 1024; j += 32) s += hsm[j] * wr[j];
#pragma unroll
        for (int off = 16; off; off >>= 1) s += __shfl_down_sync(0xffffffffu, s, off);
        if (lane == 0) g_emis[(size_t)m * CC + w] = s + cb[w];
    }
}

// ---------------- kernel 5: CRF log-likelihood (mask all-true) ---------------
__global__ void k_crf(const int* __restrict__ label, const float* __restrict__ startv,
                      const float* __restrict__ endv, const float* __restrict__ trans) {
    int b = blockIdx.x, lane = threadIdx.x;
    const int* tg = label + b * TT;
    const float* em = g_emis + (size_t)b * TT * CC;

    float p = 0.f;
    for (int t = lane; t < TT; t += 32) {
        int tag = tg[t];
        p += em[t*CC + tag];
        if (t > 0) p += trans[tg[t-1]*CC + tag];
    }
#pragma unroll
    for (int off = 16; off; off >>= 1) p += __shfl_down_sync(0xffffffffu, p, off);
    float num = __shfl_sync(0xffffffffu, p, 0);
    num += startv[tg[0]] + endv[tg[TT-1]];

    int j = (lane < CC) ? lane : 0;
    float trc[CC];
#pragma unroll
    for (int i = 0; i < CC; i++) trc[i] = trans[i*CC + j];
    float alpha = startv[j] + em[j];
    float em_next = em[CC + j];
    for (int t = 1; t < TT; t++) {
        float a[CC];
#pragma unroll
        for (int i = 0; i < CC; i++) a[i] = __shfl_sync(0xffffffffu, alpha, i) + trc[i];
        float em_t = em_next;
        if (t < TT-1) em_next = em[(t+1)*CC + j];
        float mx = a[0];
#pragma unroll
        for (int i = 1; i < CC; i++) mx = fmaxf(mx, a[i]);
        float s = 0.f;
#pragma unroll
        for (int i = 0; i < CC; i++) s += expf(a[i] - mx);
        alpha = mx + logf(s) + em_t;
    }
    float v = alpha + endv[j];
    float mv = v;
#pragma unroll
    for (int i = 0; i < CC; i++) mv = fmaxf(mv, __shfl_sync(0xffffffffu, v, i));
    float se = expf(v - mv);
    float tot = 0.f;
#pragma unroll
    for (int i = 0; i < CC; i++) tot += __shfl_sync(0xffffffffu, se, i);
    float den = mv + logf(tot);
    if (lane == 0) g_llh[b] = num - den;
}

// ---------------- kernel 6: final reduction ----------------------------------
__global__ void k_final(float* out) {
    if (threadIdx.x == 0) {
        float s = 0.f;
        for (int i = 0; i < BB; i++) s += g_llh[i];
        out[0] = -s / (float)BB;
    }
}

// ---------------- launch ------------------------------------------------------
extern "C" void kernel_launch(void* const* d_in, const int* in_sizes, int n_in,
                              void* d_out, int out_size) {
    const int*   input  = (const int*)d_in[0];
    const int*   label  = (const int*)d_in[1];
    const float* emb    = (const float*)d_in[2];
    const float* w_ih_f = (const float*)d_in[3];
    const float* w_hh_f = (const float*)d_in[4];
    const float* b_ih_f = (const float*)d_in[5];
    const float* b_hh_f = (const float*)d_in[6];
    const float* w_ih_b = (const float*)d_in[7];
    const float* w_hh_b = (const float*)d_in[8];
    const float* b_ih_b = (const float*)d_in[9];
    const float* b_hh_b = (const float*)d_in[10];
    const float* cls_w  = (const float*)d_in[11];
    const float* cls_b  = (const float*)d_in[12];
    const float* startv = (const float*)d_in[13];
    const float* endv   = (const float*)d_in[14];
    const float* trans  = (const float*)d_in[15];

    cudaFuncSetAttribute(k_lstm, cudaFuncAttributeMaxDynamicSharedMemorySize, LSTM_SMEM_BYTES);

    k_gather<<<MTOT, 128>>>(input, emb);
    k_xpgemm<<<dim3(32, 64), 256>>>(w_ih_f, w_ih_b, b_ih_f, b_hh_f, b_ih_b, b_hh_b);
    k_dummy<<<1, 32>>>();   // keeps ncu window on k_lstm
    k_lstm<<<LSTM_BLOCKS, 512, LSTM_SMEM_BYTES>>>(w_hh_f, w_hh_b);
    k_cls<<<MTOT, 288>>>(cls_w, cls_b);
    k_crf<<<BB, 32>>>(label, startv, endv, trans);
    k_final<<<1, 32>>>((float*)d_out);
}